// round 15
// baseline (speedup 1.0000x reference)
#include <cuda_runtime.h>
#include <math.h>
#include <stdint.h>

#define NODES 30000
#define EDGES 400000

// ------------------------- device scratch (static, no allocs) -------------
__device__ __align__(16) float g_cmb[NODES * 768];
__device__ __align__(16) float g_h1 [NODES * 256];
__device__ __align__(16) float g_h2 [NODES * 256];
__device__ __align__(16) float g_w0 [128 * 768];
__device__ __align__(16) float g_w1 [256 * 512];
__device__ __align__(16) float g_w2 [256 * 480];
__device__ int   g_deg[NODES];
__device__ int   g_off[NODES + 1];
__device__ int   g_cur[NODES];
__device__ int   g_srcs[EDGES];
__device__ float g_sum[256], g_sq[256], g_scale[256], g_shift[256];

// ------------------------- utility kernels --------------------------------
__global__ void zero_int_bn_kernel(int* p, int n, float* s, float* q) {
    int i = blockIdx.x * blockDim.x + threadIdx.x;
    if (i < n) p[i] = 0;
    if (i < 256) { s[i] = 0.f; q[i] = 0.f; }
}

__global__ void count_deg_kernel(const int* __restrict__ dst, int* deg, int e_cnt) {
    int e = blockIdx.x * blockDim.x + threadIdx.x;
    if (e < e_cnt) atomicAdd(&deg[dst[e]], 1);
}

__global__ void scatter_kernel(const int* __restrict__ src, const int* __restrict__ dst,
                               int* cur, int* srcs, int e_cnt) {
    int e = blockIdx.x * blockDim.x + threadIdx.x;
    if (e < e_cnt) {
        int pos = atomicAdd(&cur[dst[e]], 1);
        srcs[pos] = src[e];
    }
}

#define PACK0 (128 * 768)
#define PACK1 (256 * 512)
#define PACK2 (256 * 480)
#define PACK_TOTAL (PACK0 + PACK1 + PACK2)
__global__ void pack_all_kernel(
    const float* __restrict__ Wsrc0, const float* __restrict__ Wdst0,
    const float* __restrict__ resW0,
    const float* __restrict__ Wsrc1, const float* __restrict__ Wdst1,
    const float* __restrict__ Wsrc2, const float* __restrict__ Wdst2,
    const float* __restrict__ resW2,
    float* __restrict__ w0, float* __restrict__ w1, float* __restrict__ w2)
{
    int i = blockIdx.x * blockDim.x + threadIdx.x;
    if (i < PACK0) {
        int k = i / 768, j = i - k * 768;
        float v;
        if (j < 256)      v = Wsrc0[k * 256 + j];
        else if (j < 512) v = Wdst0[k * 256 + j - 256];
        else              v = resW0[k * 256 + j - 512];
        w0[i] = v;
    } else if (i < PACK0 + PACK1) {
        int t = i - PACK0;
        int k = t / 512, j = t - k * 512;
        w1[t] = (j < 256) ? Wsrc1[k * 256 + j] : Wdst1[k * 256 + j - 256];
    } else if (i < PACK_TOTAL) {
        int t = i - PACK0 - PACK1;
        int k = t / 480, j = t - k * 480;
        float v;
        if (j < 160)      v = Wsrc2[k * 160 + j];
        else if (j < 320) v = Wdst2[k * 160 + j - 160];
        else              v = resW2[k * 160 + j - 320];
        w2[t] = v;
    }
}

__global__ void scan_kernel(const int* __restrict__ deg, int* off, int* cur, int n) {
    __shared__ int wsum[32];
    __shared__ int carrySh;
    int tid = threadIdx.x;
    int lane = tid & 31, w = tid >> 5;
    if (tid == 0) { off[0] = 0; carrySh = 0; }
    __syncthreads();
    for (int base = 0; base < n; base += 1024) {
        int i = base + tid;
        int orig = (i < n) ? deg[i] : 0;
        int v = orig;
#pragma unroll
        for (int o = 1; o < 32; o <<= 1) {
            int t = __shfl_up_sync(0xffffffffu, v, o);
            if (lane >= o) v += t;
        }
        if (lane == 31) wsum[w] = v;
        __syncthreads();
        if (w == 0) {
            int s = wsum[lane];
#pragma unroll
            for (int o = 1; o < 32; o <<= 1) {
                int t = __shfl_up_sync(0xffffffffu, s, o);
                if (lane >= o) s += t;
            }
            wsum[lane] = s;
        }
        __syncthreads();
        int carry = carrySh;
        int add = carry + (w > 0 ? wsum[w - 1] : 0);
        if (i < n) {
            off[i + 1] = add + v;
            cur[i] = add + v - orig;
        }
        __syncthreads();
        if (tid == 0) carrySh = carry + wsum[31];
        __syncthreads();
    }
}

// ------------------------- TF32 tensor-core GEMM ---------------------------
// BNA=false: A via cp.async (raw). BNA=true: A via LDG -> BN affine+relu ->
// STS (h stays raw in gmem). B always cp.async. BM=128 BN=128 BK=32.
#define AS_STRIDE 36
#define BS_STRIDE 136
#define AS_BUF (128 * AS_STRIDE)
#define BS_BUF (32 * BS_STRIDE)
#define GEMM_SMEM ((2 * AS_BUF + 2 * BS_BUF) * 4)

__device__ __forceinline__ void cp_async16(uint32_t saddr, const void* gptr, bool pred) {
    int sz = pred ? 16 : 0;
    asm volatile("cp.async.cg.shared.global [%0], [%1], 16, %2;\n"
                 :: "r"(saddr), "l"(gptr), "r"(sz));
}

template <bool BNA>
__global__ __launch_bounds__(256, 2) void tf32_gemm_kernel(
    const float* __restrict__ A, const float* __restrict__ B,
    float* __restrict__ C, int M, int N, int K,
    const float* __restrict__ bnscale, const float* __restrict__ bnshift)
{
    extern __shared__ float sm[];
    float* As = sm;
    float* Bs = sm + 2 * AS_BUF;
    uint32_t asBase = (uint32_t)__cvta_generic_to_shared(As);
    uint32_t bsBase = (uint32_t)__cvta_generic_to_shared(Bs);

    const int tid  = threadIdx.x;
    const int lane = tid & 31;
    const int wid  = tid >> 5;
    const int warpM = wid & 1;
    const int warpN = wid >> 1;
    const int g  = lane >> 2;
    const int tg = lane & 3;

    const int m0 = blockIdx.y * 128;
    const int n0 = blockIdx.x * 128;

    const int a_seg  = tid & 7;
    const int a_row0 = tid >> 3;
    const int b_c4   = tid & 31;
    const int b_kr0  = tid >> 5;

    float acc[4][4][4];
#pragma unroll
    for (int i = 0; i < 4; i++)
#pragma unroll
        for (int j = 0; j < 4; j++)
#pragma unroll
            for (int k = 0; k < 4; k++) acc[i][j][k] = 0.f;

    float4 areg[4];

    auto ldgA = [&](int KT) {
#pragma unroll
        for (int it = 0; it < 4; it++) {
            int grow = m0 + a_row0 + 32 * it;
            if (grow < M)
                areg[it] = *(const float4*)(A + (size_t)grow * K + KT + a_seg * 4);
            else
                areg[it] = make_float4(0.f, 0.f, 0.f, 0.f);
        }
    };
    auto stsA = [&](int KT, int BUF) {
        float4 sc = *(const float4*)(bnscale + KT + a_seg * 4);
        float4 sh = *(const float4*)(bnshift + KT + a_seg * 4);
#pragma unroll
        for (int it = 0; it < 4; it++) {
            float4 v = areg[it];
            v.x = fmaxf(fmaf(v.x, sc.x, sh.x), 0.f);
            v.y = fmaxf(fmaf(v.y, sc.y, sh.y), 0.f);
            v.z = fmaxf(fmaf(v.z, sc.z, sh.z), 0.f);
            v.w = fmaxf(fmaf(v.w, sc.w, sh.w), 0.f);
            *(float4*)&As[(size_t)BUF * AS_BUF + (a_row0 + 32 * it) * AS_STRIDE + a_seg * 4] = v;
        }
    };

#define LOAD_A_ASYNC(KT, BUF)                                                   \
    {                                                                           \
        _Pragma("unroll")                                                       \
        for (int it = 0; it < 4; it++) {                                        \
            int row = a_row0 + 32 * it;                                         \
            int grow = m0 + row;                                                \
            bool p = (grow < M);                                                \
            const float* gp = A + (size_t)(p ? grow : 0) * K + (KT) + a_seg * 4;\
            cp_async16(asBase + ((BUF) * AS_BUF + row * AS_STRIDE + a_seg * 4) * 4, gp, p); \
        }                                                                       \
    }
#define LOAD_B_ASYNC(KT, BUF)                                                   \
    {                                                                           \
        _Pragma("unroll")                                                       \
        for (int it = 0; it < 4; it++) {                                        \
            int kr = b_kr0 + 8 * it;                                            \
            int col = n0 + b_c4 * 4;                                            \
            bool p = (col < N);                                                 \
            const float* gp = B + (size_t)((KT) + kr) * N + (p ? col : 0);      \
            cp_async16(bsBase + ((BUF) * BS_BUF + kr * BS_STRIDE + b_c4 * 4) * 4, gp, p); \
        }                                                                       \
    }

    const int ntiles = K >> 5;

    if (BNA) {
        ldgA(0);
        LOAD_B_ASYNC(0, 0)
        asm volatile("cp.async.commit_group;\n");
        stsA(0, 0);
    } else {
        LOAD_A_ASYNC(0, 0)
        LOAD_B_ASYNC(0, 0)
        asm volatile("cp.async.commit_group;\n");
    }

    for (int t = 0; t < ntiles; t++) {
        const int buf = t & 1;
        asm volatile("cp.async.wait_group 0;\n");
        __syncthreads();
        if (t + 1 < ntiles) {
            if (BNA) {
                ldgA((t + 1) * 32);
                LOAD_B_ASYNC((t + 1) * 32, buf ^ 1)
            } else {
                LOAD_A_ASYNC((t + 1) * 32, buf ^ 1)
                LOAD_B_ASYNC((t + 1) * 32, buf ^ 1)
            }
            asm volatile("cp.async.commit_group;\n");
        }

        const float* Ab = As + buf * AS_BUF;
        const float* Bb = Bs + buf * BS_BUF;
#pragma unroll
        for (int ks = 0; ks < 4; ks++) {
            const int kk = ks * 8;
            uint32_t bf[4][2];
#pragma unroll
            for (int nt = 0; nt < 4; nt++) {
                int nc = warpN * 32 + nt * 8 + g;
                bf[nt][0] = __float_as_uint(Bb[(kk + tg) * BS_STRIDE + nc]);
                bf[nt][1] = __float_as_uint(Bb[(kk + tg + 4) * BS_STRIDE + nc]);
            }
#pragma unroll
            for (int mt = 0; mt < 4; mt++) {
                uint32_t af0, af1, af2, af3;
                {
                    int mr = warpM * 64 + mt * 16 + g;
                    af0 = __float_as_uint(Ab[mr * AS_STRIDE + kk + tg]);
                    af1 = __float_as_uint(Ab[(mr + 8) * AS_STRIDE + kk + tg]);
                    af2 = __float_as_uint(Ab[mr * AS_STRIDE + kk + tg + 4]);
                    af3 = __float_as_uint(Ab[(mr + 8) * AS_STRIDE + kk + tg + 4]);
                }
#pragma unroll
                for (int nt = 0; nt < 4; nt++) {
                    asm volatile(
                        "mma.sync.aligned.m16n8k8.row.col.f32.tf32.tf32.f32 "
                        "{%0,%1,%2,%3}, {%4,%5,%6,%7}, {%8,%9}, {%0,%1,%2,%3};"
                        : "+f"(acc[mt][nt][0]), "+f"(acc[mt][nt][1]),
                          "+f"(acc[mt][nt][2]), "+f"(acc[mt][nt][3])
                        : "r"(af0), "r"(af1), "r"(af2), "r"(af3),
                          "r"(bf[nt][0]), "r"(bf[nt][1]));
                }
            }
        }
        if (BNA && (t + 1 < ntiles))
            stsA((t + 1) * 32, buf ^ 1);
        __syncthreads();
    }

#pragma unroll
    for (int mt = 0; mt < 4; mt++) {
        int r0 = m0 + warpM * 64 + mt * 16 + g;
#pragma unroll
        for (int nt = 0; nt < 4; nt++) {
            int cc = n0 + warpN * 32 + nt * 8 + 2 * tg;
            if (cc < N) {
                if (r0 < M) {
                    float2 v = make_float2(acc[mt][nt][0], acc[mt][nt][1]);
                    *(float2*)(C + (size_t)r0 * N + cc) = v;
                }
                if (r0 + 8 < M) {
                    float2 v = make_float2(acc[mt][nt][2], acc[mt][nt][3]);
                    *(float2*)(C + (size_t)(r0 + 8) * N + cc) = v;
                }
            }
        }
    }
}

// ------------------------- GATv2 edge kernel (2-edge unrolled) ------------
template <int DPL, bool VEC, bool RELU, bool STATS, bool FINAL, bool RESBN>
__global__ __launch_bounds__(256) void gat_edge_kernel(
    const float* __restrict__ fs, const float* __restrict__ fd,
    const float* __restrict__ res, int fsStride, int resStride,
    const float* __restrict__ bias, const float* __restrict__ attn,
    const float* __restrict__ rscale, const float* __restrict__ rshift,
    const int* __restrict__ off, const int* __restrict__ srcs,
    float* __restrict__ out, float* __restrict__ sums, float* __restrict__ sqs,
    int n_nodes)
{
    const int OUTD = DPL * 8;
    const int F = OUTD * 4;
    __shared__ float sm_s[256], sm_q[256];

    int v = (blockIdx.x * blockDim.x + threadIdx.x) >> 5;
    int lane = threadIdx.x & 31;
    const bool valid = v < n_nodes;

    if (STATS) {
        sm_s[threadIdx.x] = 0.f;
        sm_q[threadIdx.x] = 0.f;
        __syncthreads();
    }

    const int h = lane >> 3;
    const int q = lane & 7;
    const int col0 = h * OUTD + q * DPL;

    float o[DPL];

    if (valid) {
        float fdv[DPL], resv[DPL], attnr[DPL], biasr[DPL], acc[DPL];
#pragma unroll
        for (int j = 0; j < DPL; j++) {
            fdv[j]   = fd[(size_t)v * fsStride + col0 + j];
            float rv = res[(size_t)v * resStride + col0 + j];
            if (RESBN)
                rv = fmaxf(fmaf(rv, rscale[col0 + j], rshift[col0 + j]), 0.f);
            resv[j]  = rv;
            attnr[j] = attn[col0 + j];
            biasr[j] = bias[col0 + j];
            acc[j]   = 0.f;
        }

        float m = -INFINITY, s = 0.f;

        int e0 = off[v], e1 = off[v + 1];
        int e = e0;
        for (; e + 1 < e1; e += 2) {
            int u0 = srcs[e], u1 = srcs[e + 1];
            const float* f0 = fs + (size_t)u0 * fsStride + col0;
            const float* f1 = fs + (size_t)u1 * fsStride + col0;
            float a0[DPL], a1[DPL];
            if (VEC) {
                float4 x0 = *(const float4*)(f0);
                float4 x1 = *(const float4*)(f0 + 4);
                float4 y0 = *(const float4*)(f1);
                float4 y1 = *(const float4*)(f1 + 4);
                a0[0] = x0.x; a0[1] = x0.y; a0[2] = x0.z; a0[3] = x0.w;
                a0[4] = x1.x; a0[5] = x1.y; a0[6] = x1.z; a0[7 < DPL ? 7 : 0] = x1.w;
                a1[0] = y0.x; a1[1] = y0.y; a1[2] = y0.z; a1[3] = y0.w;
                a1[4] = y1.x; a1[5] = y1.y; a1[6] = y1.z; a1[7 < DPL ? 7 : 0] = y1.w;
            } else {
#pragma unroll
                for (int j = 0; j < DPL; j++) { a0[j] = f0[j]; a1[j] = f1[j]; }
            }

            float p0 = 0.f, p1 = 0.f;
#pragma unroll
            for (int j = 0; j < DPL; j++) {
                float t0 = a0[j] + fdv[j];
                float t1 = a1[j] + fdv[j];
                float l0 = fmaxf(t0, 0.2f * t0);
                float l1 = fmaxf(t1, 0.2f * t1);
                p0 = fmaf(attnr[j], l0, p0);
                p1 = fmaf(attnr[j], l1, p1);
            }
            p0 += __shfl_xor_sync(0xffffffffu, p0, 1);
            p1 += __shfl_xor_sync(0xffffffffu, p1, 1);
            p0 += __shfl_xor_sync(0xffffffffu, p0, 2);
            p1 += __shfl_xor_sync(0xffffffffu, p1, 2);
            p0 += __shfl_xor_sync(0xffffffffu, p0, 4);
            p1 += __shfl_xor_sync(0xffffffffu, p1, 4);

            float pm = fmaxf(p0, p1);
            float nm = fmaxf(m, pm);
            float sc = __expf(m - nm);
            float w0 = __expf(p0 - nm);
            float w1 = __expf(p1 - nm);
            s = s * sc + w0 + w1;
            m = nm;
#pragma unroll
            for (int j = 0; j < DPL; j++)
                acc[j] = fmaf(acc[j], sc, fmaf(w0, a0[j], w1 * a1[j]));
        }
        if (e < e1) {
            int u = srcs[e];
            const float* frow = fs + (size_t)u * fsStride + col0;
            float fsu[DPL];
            if (VEC) {
                float4 v0 = *(const float4*)(frow);
                float4 v1 = *(const float4*)(frow + 4);
                fsu[0] = v0.x; fsu[1] = v0.y; fsu[2] = v0.z; fsu[3] = v0.w;
                fsu[4] = v1.x; fsu[5] = v1.y; fsu[6] = v1.z; fsu[7 < DPL ? 7 : 0] = v1.w;
            } else {
#pragma unroll
                for (int j = 0; j < DPL; j++) fsu[j] = frow[j];
            }
            float p = 0.f;
#pragma unroll
            for (int j = 0; j < DPL; j++) {
                float t = fsu[j] + fdv[j];
                float lr = fmaxf(t, 0.2f * t);
                p = fmaf(attnr[j], lr, p);
            }
            p += __shfl_xor_sync(0xffffffffu, p, 1);
            p += __shfl_xor_sync(0xffffffffu, p, 2);
            p += __shfl_xor_sync(0xffffffffu, p, 4);

            float nm = fmaxf(m, p);
            float sc = __expf(m - nm);
            float w  = __expf(p - nm);
            s = s * sc + w;
            m = nm;
#pragma unroll
            for (int j = 0; j < DPL; j++)
                acc[j] = fmaf(acc[j], sc, w * fsu[j]);
        }

        float r = 1.f / fmaxf(s, 1e-9f);
#pragma unroll
        for (int j = 0; j < DPL; j++) {
            o[j] = fmaf(acc[j], r, resv[j] + biasr[j]);
            if (RELU) o[j] = fmaxf(o[j], 0.f);
        }

        if (!FINAL) {
#pragma unroll
            for (int j = 0; j < DPL; j++)
                out[(size_t)v * F + col0 + j] = o[j];
        }
    }

    if (FINAL) {
        float vv[DPL];
#pragma unroll
        for (int j = 0; j < DPL; j++) {
            float t = valid ? o[j] : 0.f;
            t += __shfl_xor_sync(0xffffffffu, t, 8);
            t += __shfl_xor_sync(0xffffffffu, t, 16);
            vv[j] = 0.25f * t;
        }
        float mx = vv[0];
#pragma unroll
        for (int j = 1; j < DPL; j++) mx = fmaxf(mx, vv[j]);
        mx = fmaxf(mx, __shfl_xor_sync(0xffffffffu, mx, 1));
        mx = fmaxf(mx, __shfl_xor_sync(0xffffffffu, mx, 2));
        mx = fmaxf(mx, __shfl_xor_sync(0xffffffffu, mx, 4));
        float es = 0.f;
#pragma unroll
        for (int j = 0; j < DPL; j++) es += expf(vv[j] - mx);
        es += __shfl_xor_sync(0xffffffffu, es, 1);
        es += __shfl_xor_sync(0xffffffffu, es, 2);
        es += __shfl_xor_sync(0xffffffffu, es, 4);
        float lse = mx + logf(es);
        if (valid && h == 0) {
#pragma unroll
            for (int j = 0; j < DPL; j++)
                out[(size_t)v * 40 + q * DPL + j] = vv[j] - lse;
        }
    }

    if (STATS) {
        if (valid) {
#pragma unroll
            for (int j = 0; j < DPL; j++) {
                atomicAdd(&sm_s[col0 + j], o[j]);
                atomicAdd(&sm_q[col0 + j], o[j] * o[j]);
            }
        }
        __syncthreads();
        atomicAdd(&sums[threadIdx.x], sm_s[threadIdx.x]);
        atomicAdd(&sqs[threadIdx.x],  sm_q[threadIdx.x]);
    }
}

// ------------------------- batchnorm finalize (also zeroes stats) ----------
__global__ void bn_finalize_kernel(float* sums, float* sqs,
                                   const float* __restrict__ g, const float* __restrict__ be,
                                   float* scale, float* shift, int n) {
    int f = threadIdx.x;
    float mean = sums[f] / (float)n;
    float var  = sqs[f] / (float)n - mean * mean;
    float sc = g[f] * rsqrtf(var + 1e-5f);
    scale[f] = sc;
    shift[f] = be[f] - mean * sc;
    sums[f] = 0.f;
    sqs[f]  = 0.f;
}

// ------------------------- host orchestration ------------------------------
template <bool BNA>
static inline void launch_gemm(const float* A, const float* B, float* C,
                               int M, int N, int K,
                               const float* sc, const float* sh, cudaStream_t st) {
    dim3 grid((N + 127) / 128, (M + 127) / 128);
    tf32_gemm_kernel<BNA><<<grid, 256, GEMM_SMEM, st>>>(A, B, C, M, N, K, sc, sh);
}

extern "C" void kernel_launch(void* const* d_in, const int* in_sizes, int n_in,
                              void* d_out, int out_size) {
    const float* x      = (const float*)d_in[0];
    const int*   src    = (const int*)d_in[1];
    const int*   dst    = (const int*)d_in[2];
    const float* Wsrc0  = (const float*)d_in[3];
    const float* Wdst0  = (const float*)d_in[4];
    const float* b0     = (const float*)d_in[5];
    const float* attn0  = (const float*)d_in[6];
    const float* resW0  = (const float*)d_in[7];
    const float* Wsrc1  = (const float*)d_in[8];
    const float* Wdst1  = (const float*)d_in[9];
    const float* b1     = (const float*)d_in[10];
    const float* attn1  = (const float*)d_in[11];
    const float* Wsrc2  = (const float*)d_in[12];
    const float* Wdst2  = (const float*)d_in[13];
    const float* b2     = (const float*)d_in[14];
    const float* attn2  = (const float*)d_in[15];
    const float* resW2  = (const float*)d_in[16];
    const float* g0     = (const float*)d_in[17];
    const float* be0    = (const float*)d_in[18];
    const float* g1     = (const float*)d_in[19];
    const float* be1    = (const float*)d_in[20];
    float* out = (float*)d_out;

    const int NN = in_sizes[0] / 128;
    const int EE = in_sizes[1];

    static int inited = 0;
    static cudaStream_t s1;
    static cudaEvent_t evFork, evJoin;
    if (!inited) {
        cudaFuncSetAttribute(tf32_gemm_kernel<false>,
                             cudaFuncAttributeMaxDynamicSharedMemorySize, GEMM_SMEM);
        cudaFuncSetAttribute(tf32_gemm_kernel<true>,
                             cudaFuncAttributeMaxDynamicSharedMemorySize, GEMM_SMEM);
        cudaStreamCreateWithFlags(&s1, cudaStreamNonBlocking);
        cudaEventCreateWithFlags(&evFork, cudaEventDisableTiming);
        cudaEventCreateWithFlags(&evJoin, cudaEventDisableTiming);
        inited = 1;
    }

    float *cmb, *h1, *h2, *w0, *w1, *w2;
    int *deg, *off, *cur, *srcs;
    float *bsum, *bsq, *bscale, *bshift;
    cudaGetSymbolAddress((void**)&cmb, g_cmb);
    cudaGetSymbolAddress((void**)&h1,  g_h1);
    cudaGetSymbolAddress((void**)&h2,  g_h2);
    cudaGetSymbolAddress((void**)&w0,  g_w0);
    cudaGetSymbolAddress((void**)&w1,  g_w1);
    cudaGetSymbolAddress((void**)&w2,  g_w2);
    cudaGetSymbolAddress((void**)&deg, g_deg);
    cudaGetSymbolAddress((void**)&off, g_off);
    cudaGetSymbolAddress((void**)&cur, g_cur);
    cudaGetSymbolAddress((void**)&srcs, g_srcs);
    cudaGetSymbolAddress((void**)&bsum, g_sum);
    cudaGetSymbolAddress((void**)&bsq,  g_sq);
    cudaGetSymbolAddress((void**)&bscale, g_scale);
    cudaGetSymbolAddress((void**)&bshift, g_shift);

    const int TB = 256;
    const int nodeBlocks = (NN + TB - 1) / TB;
    const int edgeBlocks = (EE + TB - 1) / TB;
    const int warpNodeBlocks = (NN * 32 + TB - 1) / TB;

    // Fork: CSR build on s1 overlaps pack+gemm0 on main stream.
    cudaEventRecord(evFork, 0);
    cudaStreamWaitEvent(s1, evFork, 0);

    zero_int_bn_kernel<<<nodeBlocks, TB, 0, s1>>>(deg, NN, bsum, bsq);
    count_deg_kernel<<<edgeBlocks, TB, 0, s1>>>(dst, deg, EE);
    scan_kernel<<<1, 1024, 0, s1>>>(deg, off, cur, NN);
    scatter_kernel<<<edgeBlocks, TB, 0, s1>>>(src, dst, cur, srcs, EE);
    cudaEventRecord(evJoin, s1);

    pack_all_kernel<<<(PACK_TOTAL + TB - 1) / TB, TB>>>(
        Wsrc0, Wdst0, resW0, Wsrc1, Wdst1, Wsrc2, Wdst2, resW2, w0, w1, w2);
    launch_gemm<false>(x, w0, cmb, NN, 768, 128, nullptr, nullptr, 0);

    cudaStreamWaitEvent(0, evJoin, 0);

    // ---- layer 0 edges (+BN stats); h1 stays RAW (pre-BN) ----
    gat_edge_kernel<8, true, true, true, false, false><<<warpNodeBlocks, TB>>>(
        cmb, cmb + 256, cmb + 512, 768, 768, b0, attn0, nullptr, nullptr,
        off, srcs, h1, bsum, bsq, NN);
    bn_finalize_kernel<<<1, 256>>>(bsum, bsq, g0, be0, bscale, bshift, NN);

    // ---- layer 1: GEMM applies BN0+relu to A; edge applies BN0 to res ----
    launch_gemm<true>(h1, w1, cmb, NN, 512, 256, bscale, bshift, 0);
    gat_edge_kernel<8, true, true, true, false, true><<<warpNodeBlocks, TB>>>(
        cmb, cmb + 256, h1, 512, 256, b1, attn1, bscale, bshift,
        off, srcs, h2, bsum, bsq, NN);
    bn_finalize_kernel<<<1, 256>>>(bsum, bsq, g1, be1, bscale, bshift, NN);

    // ---- layer 2: GEMM applies BN1+relu to A; fused final edge ----
    launch_gemm<true>(h2, w2, cmb, NN, 480, 256, bscale, bshift, 0);
    gat_edge_kernel<5, false, false, false, true, false><<<warpNodeBlocks, TB>>>(
        cmb, cmb + 160, cmb + 320, 480, 480, b2, attn2, nullptr, nullptr,
        off, srcs, out, nullptr, nullptr, NN);

    (void)n_in; (void)out_size;
}

// round 16
// speedup vs baseline: 1.0751x; 1.0751x over previous
#include <cuda_runtime.h>
#include <math.h>
#include <stdint.h>

#define NODES 30000
#define EDGES 400000

// ------------------------- device scratch (static, no allocs) -------------
__device__ __align__(16) float g_cmb[NODES * 768];
__device__ __align__(16) float g_h1 [NODES * 256];
__device__ __align__(16) float g_h2 [NODES * 256];
__device__ __align__(16) float g_w0 [128 * 768];
__device__ __align__(16) float g_w1 [256 * 512];
__device__ __align__(16) float g_w2 [256 * 480];
__device__ int   g_deg[NODES];
__device__ int   g_off[NODES + 1];
__device__ int   g_cur[NODES];
__device__ int   g_srcs[EDGES];
__device__ float g_sum[512], g_sq[512];   // [0:256)=layer0 stats, [256:512)=layer1

// ------------------------- utility kernels --------------------------------
__global__ void zero_int_bn_kernel(int* p, int n, float* s, float* q) {
    int i = blockIdx.x * blockDim.x + threadIdx.x;
    if (i < n) p[i] = 0;
    if (i < 512) { s[i] = 0.f; q[i] = 0.f; }
}

__global__ void count_deg_kernel(const int* __restrict__ dst, int* deg, int e_cnt) {
    int e = blockIdx.x * blockDim.x + threadIdx.x;
    if (e < e_cnt) atomicAdd(&deg[dst[e]], 1);
}

__global__ void scatter_kernel(const int* __restrict__ src, const int* __restrict__ dst,
                               int* cur, int* srcs, int e_cnt) {
    int e = blockIdx.x * blockDim.x + threadIdx.x;
    if (e < e_cnt) {
        int pos = atomicAdd(&cur[dst[e]], 1);
        srcs[pos] = src[e];
    }
}

#define PACK0 (128 * 768)
#define PACK1 (256 * 512)
#define PACK2 (256 * 480)
#define PACK_TOTAL (PACK0 + PACK1 + PACK2)
__global__ void pack_all_kernel(
    const float* __restrict__ Wsrc0, const float* __restrict__ Wdst0,
    const float* __restrict__ resW0,
    const float* __restrict__ Wsrc1, const float* __restrict__ Wdst1,
    const float* __restrict__ Wsrc2, const float* __restrict__ Wdst2,
    const float* __restrict__ resW2,
    float* __restrict__ w0, float* __restrict__ w1, float* __restrict__ w2)
{
    int i = blockIdx.x * blockDim.x + threadIdx.x;
    if (i < PACK0) {
        int k = i / 768, j = i - k * 768;
        float v;
        if (j < 256)      v = Wsrc0[k * 256 + j];
        else if (j < 512) v = Wdst0[k * 256 + j - 256];
        else              v = resW0[k * 256 + j - 512];
        w0[i] = v;
    } else if (i < PACK0 + PACK1) {
        int t = i - PACK0;
        int k = t / 512, j = t - k * 512;
        w1[t] = (j < 256) ? Wsrc1[k * 256 + j] : Wdst1[k * 256 + j - 256];
    } else if (i < PACK_TOTAL) {
        int t = i - PACK0 - PACK1;
        int k = t / 480, j = t - k * 480;
        float v;
        if (j < 160)      v = Wsrc2[k * 160 + j];
        else if (j < 320) v = Wdst2[k * 160 + j - 160];
        else              v = resW2[k * 160 + j - 320];
        w2[t] = v;
    }
}

__global__ void scan_kernel(const int* __restrict__ deg, int* off, int* cur, int n) {
    __shared__ int wsum[32];
    __shared__ int carrySh;
    int tid = threadIdx.x;
    int lane = tid & 31, w = tid >> 5;
    if (tid == 0) { off[0] = 0; carrySh = 0; }
    __syncthreads();
    for (int base = 0; base < n; base += 1024) {
        int i = base + tid;
        int orig = (i < n) ? deg[i] : 0;
        int v = orig;
#pragma unroll
        for (int o = 1; o < 32; o <<= 1) {
            int t = __shfl_up_sync(0xffffffffu, v, o);
            if (lane >= o) v += t;
        }
        if (lane == 31) wsum[w] = v;
        __syncthreads();
        if (w == 0) {
            int s = wsum[lane];
#pragma unroll
            for (int o = 1; o < 32; o <<= 1) {
                int t = __shfl_up_sync(0xffffffffu, s, o);
                if (lane >= o) s += t;
            }
            wsum[lane] = s;
        }
        __syncthreads();
        int carry = carrySh;
        int add = carry + (w > 0 ? wsum[w - 1] : 0);
        if (i < n) {
            off[i + 1] = add + v;
            cur[i] = add + v - orig;
        }
        __syncthreads();
        if (tid == 0) carrySh = carry + wsum[31];
        __syncthreads();
    }
}

// ------------------------- TF32 tensor-core GEMM ---------------------------
// BNA=false: A via cp.async (raw). BNA=true: A via LDG -> BN affine+relu ->
// STS; scale/shift computed in-kernel from raw sums/sqs (smem).
#define AS_STRIDE 36
#define BS_STRIDE 136
#define AS_BUF (128 * AS_STRIDE)
#define BS_BUF (32 * BS_STRIDE)
#define GEMM_SMEM ((2 * AS_BUF + 2 * BS_BUF + 512) * 4)

__device__ __forceinline__ void cp_async16(uint32_t saddr, const void* gptr, bool pred) {
    int sz = pred ? 16 : 0;
    asm volatile("cp.async.cg.shared.global [%0], [%1], 16, %2;\n"
                 :: "r"(saddr), "l"(gptr), "r"(sz));
}

template <bool BNA>
__global__ __launch_bounds__(256, 2) void tf32_gemm_kernel(
    const float* __restrict__ A, const float* __restrict__ B,
    float* __restrict__ C, int M, int N, int K,
    const float* __restrict__ sums, const float* __restrict__ sqs,
    const float* __restrict__ gam, const float* __restrict__ bet, float inv_n)
{
    extern __shared__ float sm[];
    float* As = sm;
    float* Bs = sm + 2 * AS_BUF;
    float* bsc = sm + 2 * AS_BUF + 2 * BS_BUF;   // [256]
    float* bsh = bsc + 256;                       // [256]
    uint32_t asBase = (uint32_t)__cvta_generic_to_shared(As);
    uint32_t bsBase = (uint32_t)__cvta_generic_to_shared(Bs);

    const int tid  = threadIdx.x;
    const int lane = tid & 31;
    const int wid  = tid >> 5;
    const int warpM = wid & 1;
    const int warpN = wid >> 1;
    const int g  = lane >> 2;
    const int tg = lane & 3;

    if (BNA) {
        // K == 256 for BNA layers; one feature per thread
        float mean = sums[tid] * inv_n;
        float var  = sqs[tid] * inv_n - mean * mean;
        float sc = gam[tid] * rsqrtf(var + 1e-5f);
        bsc[tid] = sc;
        bsh[tid] = bet[tid] - mean * sc;
        __syncthreads();
    }

    const int m0 = blockIdx.y * 128;
    const int n0 = blockIdx.x * 128;

    const int a_seg  = tid & 7;
    const int a_row0 = tid >> 3;
    const int b_c4   = tid & 31;
    const int b_kr0  = tid >> 5;

    float acc[4][4][4];
#pragma unroll
    for (int i = 0; i < 4; i++)
#pragma unroll
        for (int j = 0; j < 4; j++)
#pragma unroll
            for (int k = 0; k < 4; k++) acc[i][j][k] = 0.f;

    float4 areg[4];

    auto ldgA = [&](int KT) {
#pragma unroll
        for (int it = 0; it < 4; it++) {
            int grow = m0 + a_row0 + 32 * it;
            if (grow < M)
                areg[it] = *(const float4*)(A + (size_t)grow * K + KT + a_seg * 4);
            else
                areg[it] = make_float4(0.f, 0.f, 0.f, 0.f);
        }
    };
    auto stsA = [&](int KT, int BUF) {
        float4 sc = *(const float4*)(bsc + KT + a_seg * 4);
        float4 sh = *(const float4*)(bsh + KT + a_seg * 4);
#pragma unroll
        for (int it = 0; it < 4; it++) {
            float4 v = areg[it];
            v.x = fmaxf(fmaf(v.x, sc.x, sh.x), 0.f);
            v.y = fmaxf(fmaf(v.y, sc.y, sh.y), 0.f);
            v.z = fmaxf(fmaf(v.z, sc.z, sh.z), 0.f);
            v.w = fmaxf(fmaf(v.w, sc.w, sh.w), 0.f);
            *(float4*)&As[(size_t)BUF * AS_BUF + (a_row0 + 32 * it) * AS_STRIDE + a_seg * 4] = v;
        }
    };

#define LOAD_A_ASYNC(KT, BUF)                                                   \
    {                                                                           \
        _Pragma("unroll")                                                       \
        for (int it = 0; it < 4; it++) {                                        \
            int row = a_row0 + 32 * it;                                         \
            int grow = m0 + row;                                                \
            bool p = (grow < M);                                                \
            const float* gp = A + (size_t)(p ? grow : 0) * K + (KT) + a_seg * 4;\
            cp_async16(asBase + ((BUF) * AS_BUF + row * AS_STRIDE + a_seg * 4) * 4, gp, p); \
        }                                                                       \
    }
#define LOAD_B_ASYNC(KT, BUF)                                                   \
    {                                                                           \
        _Pragma("unroll")                                                       \
        for (int it = 0; it < 4; it++) {                                        \
            int kr = b_kr0 + 8 * it;                                            \
            int col = n0 + b_c4 * 4;                                            \
            bool p = (col < N);                                                 \
            const float* gp = B + (size_t)((KT) + kr) * N + (p ? col : 0);      \
            cp_async16(bsBase + ((BUF) * BS_BUF + kr * BS_STRIDE + b_c4 * 4) * 4, gp, p); \
        }                                                                       \
    }

    const int ntiles = K >> 5;

    if (BNA) {
        ldgA(0);
        LOAD_B_ASYNC(0, 0)
        asm volatile("cp.async.commit_group;\n");
        stsA(0, 0);
    } else {
        LOAD_A_ASYNC(0, 0)
        LOAD_B_ASYNC(0, 0)
        asm volatile("cp.async.commit_group;\n");
    }

    for (int t = 0; t < ntiles; t++) {
        const int buf = t & 1;
        asm volatile("cp.async.wait_group 0;\n");
        __syncthreads();
        if (t + 1 < ntiles) {
            if (BNA) {
                ldgA((t + 1) * 32);
                LOAD_B_ASYNC((t + 1) * 32, buf ^ 1)
            } else {
                LOAD_A_ASYNC((t + 1) * 32, buf ^ 1)
                LOAD_B_ASYNC((t + 1) * 32, buf ^ 1)
            }
            asm volatile("cp.async.commit_group;\n");
        }

        const float* Ab = As + buf * AS_BUF;
        const float* Bb = Bs + buf * BS_BUF;
#pragma unroll
        for (int ks = 0; ks < 4; ks++) {
            const int kk = ks * 8;
            uint32_t bf[4][2];
#pragma unroll
            for (int nt = 0; nt < 4; nt++) {
                int nc = warpN * 32 + nt * 8 + g;
                bf[nt][0] = __float_as_uint(Bb[(kk + tg) * BS_STRIDE + nc]);
                bf[nt][1] = __float_as_uint(Bb[(kk + tg + 4) * BS_STRIDE + nc]);
            }
#pragma unroll
            for (int mt = 0; mt < 4; mt++) {
                uint32_t af0, af1, af2, af3;
                {
                    int mr = warpM * 64 + mt * 16 + g;
                    af0 = __float_as_uint(Ab[mr * AS_STRIDE + kk + tg]);
                    af1 = __float_as_uint(Ab[(mr + 8) * AS_STRIDE + kk + tg]);
                    af2 = __float_as_uint(Ab[mr * AS_STRIDE + kk + tg + 4]);
                    af3 = __float_as_uint(Ab[(mr + 8) * AS_STRIDE + kk + tg + 4]);
                }
#pragma unroll
                for (int nt = 0; nt < 4; nt++) {
                    asm volatile(
                        "mma.sync.aligned.m16n8k8.row.col.f32.tf32.tf32.f32 "
                        "{%0,%1,%2,%3}, {%4,%5,%6,%7}, {%8,%9}, {%0,%1,%2,%3};"
                        : "+f"(acc[mt][nt][0]), "+f"(acc[mt][nt][1]),
                          "+f"(acc[mt][nt][2]), "+f"(acc[mt][nt][3])
                        : "r"(af0), "r"(af1), "r"(af2), "r"(af3),
                          "r"(bf[nt][0]), "r"(bf[nt][1]));
                }
            }
        }
        if (BNA && (t + 1 < ntiles))
            stsA((t + 1) * 32, buf ^ 1);
        __syncthreads();
    }

#pragma unroll
    for (int mt = 0; mt < 4; mt++) {
        int r0 = m0 + warpM * 64 + mt * 16 + g;
#pragma unroll
        for (int nt = 0; nt < 4; nt++) {
            int cc = n0 + warpN * 32 + nt * 8 + 2 * tg;
            if (cc < N) {
                if (r0 < M) {
                    float2 v = make_float2(acc[mt][nt][0], acc[mt][nt][1]);
                    *(float2*)(C + (size_t)r0 * N + cc) = v;
                }
                if (r0 + 8 < M) {
                    float2 v = make_float2(acc[mt][nt][2], acc[mt][nt][3]);
                    *(float2*)(C + (size_t)(r0 + 8) * N + cc) = v;
                }
            }
        }
    }
}

// ------------------------- GATv2 edge kernel (2-edge unrolled) ------------
// RESBN: res is raw; BN scale/shift computed in-kernel from rsums/rsqs.
template <int DPL, bool VEC, bool RELU, bool STATS, bool FINAL, bool RESBN>
__global__ __launch_bounds__(256) void gat_edge_kernel(
    const float* __restrict__ fs, const float* __restrict__ fd,
    const float* __restrict__ res, int fsStride, int resStride,
    const float* __restrict__ bias, const float* __restrict__ attn,
    const float* __restrict__ rsums, const float* __restrict__ rsqs,
    const float* __restrict__ rg, const float* __restrict__ rbe, float inv_n,
    const int* __restrict__ off, const int* __restrict__ srcs,
    float* __restrict__ out, float* __restrict__ sums, float* __restrict__ sqs,
    int n_nodes)
{
    const int OUTD = DPL * 8;
    const int F = OUTD * 4;
    __shared__ float sm_s[256], sm_q[256];
    __shared__ float rsc[256], rsh[256];

    int v = (blockIdx.x * blockDim.x + threadIdx.x) >> 5;
    int lane = threadIdx.x & 31;
    const bool valid = v < n_nodes;

    if (STATS) {
        sm_s[threadIdx.x] = 0.f;
        sm_q[threadIdx.x] = 0.f;
    }
    if (RESBN) {
        float mean = rsums[threadIdx.x] * inv_n;
        float var  = rsqs[threadIdx.x] * inv_n - mean * mean;
        float sc = rg[threadIdx.x] * rsqrtf(var + 1e-5f);
        rsc[threadIdx.x] = sc;
        rsh[threadIdx.x] = rbe[threadIdx.x] - mean * sc;
    }
    if (STATS || RESBN) __syncthreads();

    const int h = lane >> 3;
    const int q = lane & 7;
    const int col0 = h * OUTD + q * DPL;

    float o[DPL];

    if (valid) {
        float fdv[DPL], resv[DPL], attnr[DPL], biasr[DPL], acc[DPL];
#pragma unroll
        for (int j = 0; j < DPL; j++) {
            fdv[j]   = fd[(size_t)v * fsStride + col0 + j];
            float rv = res[(size_t)v * resStride + col0 + j];
            if (RESBN)
                rv = fmaxf(fmaf(rv, rsc[col0 + j], rsh[col0 + j]), 0.f);
            resv[j]  = rv;
            attnr[j] = attn[col0 + j];
            biasr[j] = bias[col0 + j];
            acc[j]   = 0.f;
        }

        float m = -INFINITY, s = 0.f;

        int e0 = off[v], e1 = off[v + 1];
        int e = e0;
        for (; e + 1 < e1; e += 2) {
            int u0 = srcs[e], u1 = srcs[e + 1];
            const float* f0 = fs + (size_t)u0 * fsStride + col0;
            const float* f1 = fs + (size_t)u1 * fsStride + col0;
            float a0[DPL], a1[DPL];
            if (VEC) {
                float4 x0 = *(const float4*)(f0);
                float4 x1 = *(const float4*)(f0 + 4);
                float4 y0 = *(const float4*)(f1);
                float4 y1 = *(const float4*)(f1 + 4);
                a0[0] = x0.x; a0[1] = x0.y; a0[2] = x0.z; a0[3] = x0.w;
                a0[4] = x1.x; a0[5] = x1.y; a0[6] = x1.z; a0[7 < DPL ? 7 : 0] = x1.w;
                a1[0] = y0.x; a1[1] = y0.y; a1[2] = y0.z; a1[3] = y0.w;
                a1[4] = y1.x; a1[5] = y1.y; a1[6] = y1.z; a1[7 < DPL ? 7 : 0] = y1.w;
            } else {
#pragma unroll
                for (int j = 0; j < DPL; j++) { a0[j] = f0[j]; a1[j] = f1[j]; }
            }

            float p0 = 0.f, p1 = 0.f;
#pragma unroll
            for (int j = 0; j < DPL; j++) {
                float t0 = a0[j] + fdv[j];
                float t1 = a1[j] + fdv[j];
                float l0 = fmaxf(t0, 0.2f * t0);
                float l1 = fmaxf(t1, 0.2f * t1);
                p0 = fmaf(attnr[j], l0, p0);
                p1 = fmaf(attnr[j], l1, p1);
            }
            p0 += __shfl_xor_sync(0xffffffffu, p0, 1);
            p1 += __shfl_xor_sync(0xffffffffu, p1, 1);
            p0 += __shfl_xor_sync(0xffffffffu, p0, 2);
            p1 += __shfl_xor_sync(0xffffffffu, p1, 2);
            p0 += __shfl_xor_sync(0xffffffffu, p0, 4);
            p1 += __shfl_xor_sync(0xffffffffu, p1, 4);

            float pm = fmaxf(p0, p1);
            float nm = fmaxf(m, pm);
            float sc = __expf(m - nm);
            float w0 = __expf(p0 - nm);
            float w1 = __expf(p1 - nm);
            s = s * sc + w0 + w1;
            m = nm;
#pragma unroll
            for (int j = 0; j < DPL; j++)
                acc[j] = fmaf(acc[j], sc, fmaf(w0, a0[j], w1 * a1[j]));
        }
        if (e < e1) {
            int u = srcs[e];
            const float* frow = fs + (size_t)u * fsStride + col0;
            float fsu[DPL];
            if (VEC) {
                float4 v0 = *(const float4*)(frow);
                float4 v1 = *(const float4*)(frow + 4);
                fsu[0] = v0.x; fsu[1] = v0.y; fsu[2] = v0.z; fsu[3] = v0.w;
                fsu[4] = v1.x; fsu[5] = v1.y; fsu[6] = v1.z; fsu[7 < DPL ? 7 : 0] = v1.w;
            } else {
#pragma unroll
                for (int j = 0; j < DPL; j++) fsu[j] = frow[j];
            }
            float p = 0.f;
#pragma unroll
            for (int j = 0; j < DPL; j++) {
                float t = fsu[j] + fdv[j];
                float lr = fmaxf(t, 0.2f * t);
                p = fmaf(attnr[j], lr, p);
            }
            p += __shfl_xor_sync(0xffffffffu, p, 1);
            p += __shfl_xor_sync(0xffffffffu, p, 2);
            p += __shfl_xor_sync(0xffffffffu, p, 4);

            float nm = fmaxf(m, p);
            float sc = __expf(m - nm);
            float w  = __expf(p - nm);
            s = s * sc + w;
            m = nm;
#pragma unroll
            for (int j = 0; j < DPL; j++)
                acc[j] = fmaf(acc[j], sc, w * fsu[j]);
        }

        float r = 1.f / fmaxf(s, 1e-9f);
#pragma unroll
        for (int j = 0; j < DPL; j++) {
            o[j] = fmaf(acc[j], r, resv[j] + biasr[j]);
            if (RELU) o[j] = fmaxf(o[j], 0.f);
        }

        if (!FINAL) {
#pragma unroll
            for (int j = 0; j < DPL; j++)
                out[(size_t)v * F + col0 + j] = o[j];
        }
    }

    if (FINAL) {
        float vv[DPL];
#pragma unroll
        for (int j = 0; j < DPL; j++) {
            float t = valid ? o[j] : 0.f;
            t += __shfl_xor_sync(0xffffffffu, t, 8);
            t += __shfl_xor_sync(0xffffffffu, t, 16);
            vv[j] = 0.25f * t;
        }
        float mx = vv[0];
#pragma unroll
        for (int j = 1; j < DPL; j++) mx = fmaxf(mx, vv[j]);
        mx = fmaxf(mx, __shfl_xor_sync(0xffffffffu, mx, 1));
        mx = fmaxf(mx, __shfl_xor_sync(0xffffffffu, mx, 2));
        mx = fmaxf(mx, __shfl_xor_sync(0xffffffffu, mx, 4));
        float es = 0.f;
#pragma unroll
        for (int j = 0; j < DPL; j++) es += expf(vv[j] - mx);
        es += __shfl_xor_sync(0xffffffffu, es, 1);
        es += __shfl_xor_sync(0xffffffffu, es, 2);
        es += __shfl_xor_sync(0xffffffffu, es, 4);
        float lse = mx + logf(es);
        if (valid && h == 0) {
#pragma unroll
            for (int j = 0; j < DPL; j++)
                out[(size_t)v * 40 + q * DPL + j] = vv[j] - lse;
        }
    }

    if (STATS) {
        if (valid) {
#pragma unroll
            for (int j = 0; j < DPL; j++) {
                atomicAdd(&sm_s[col0 + j], o[j]);
                atomicAdd(&sm_q[col0 + j], o[j] * o[j]);
            }
        }
        __syncthreads();
        atomicAdd(&sums[threadIdx.x], sm_s[threadIdx.x]);
        atomicAdd(&sqs[threadIdx.x],  sm_q[threadIdx.x]);
    }
}

// ------------------------- host orchestration ------------------------------
template <bool BNA>
static inline void launch_gemm(const float* A, const float* B, float* C,
                               int M, int N, int K,
                               const float* sums, const float* sqs,
                               const float* gam, const float* bet, float inv_n,
                               cudaStream_t st) {
    dim3 grid((N + 127) / 128, (M + 127) / 128);
    tf32_gemm_kernel<BNA><<<grid, 256, GEMM_SMEM, st>>>(
        A, B, C, M, N, K, sums, sqs, gam, bet, inv_n);
}

extern "C" void kernel_launch(void* const* d_in, const int* in_sizes, int n_in,
                              void* d_out, int out_size) {
    const float* x      = (const float*)d_in[0];
    const int*   src    = (const int*)d_in[1];
    const int*   dst    = (const int*)d_in[2];
    const float* Wsrc0  = (const float*)d_in[3];
    const float* Wdst0  = (const float*)d_in[4];
    const float* b0     = (const float*)d_in[5];
    const float* attn0  = (const float*)d_in[6];
    const float* resW0  = (const float*)d_in[7];
    const float* Wsrc1  = (const float*)d_in[8];
    const float* Wdst1  = (const float*)d_in[9];
    const float* b1     = (const float*)d_in[10];
    const float* attn1  = (const float*)d_in[11];
    const float* Wsrc2  = (const float*)d_in[12];
    const float* Wdst2  = (const float*)d_in[13];
    const float* b2     = (const float*)d_in[14];
    const float* attn2  = (const float*)d_in[15];
    const float* resW2  = (const float*)d_in[16];
    const float* g0     = (const float*)d_in[17];
    const float* be0    = (const float*)d_in[18];
    const float* g1     = (const float*)d_in[19];
    const float* be1    = (const float*)d_in[20];
    float* out = (float*)d_out;

    const int NN = in_sizes[0] / 128;
    const int EE = in_sizes[1];
    const float inv_n = 1.f / (float)NN;

    static int inited = 0;
    static cudaStream_t s1;
    static cudaEvent_t evFork, evJoin;
    if (!inited) {
        cudaFuncSetAttribute(tf32_gemm_kernel<false>,
                             cudaFuncAttributeMaxDynamicSharedMemorySize, GEMM_SMEM);
        cudaFuncSetAttribute(tf32_gemm_kernel<true>,
                             cudaFuncAttributeMaxDynamicSharedMemorySize, GEMM_SMEM);
        cudaStreamCreateWithFlags(&s1, cudaStreamNonBlocking);
        cudaEventCreateWithFlags(&evFork, cudaEventDisableTiming);
        cudaEventCreateWithFlags(&evJoin, cudaEventDisableTiming);
        inited = 1;
    }

    float *cmb, *h1, *h2, *w0, *w1, *w2;
    int *deg, *off, *cur, *srcs;
    float *bsum, *bsq;
    cudaGetSymbolAddress((void**)&cmb, g_cmb);
    cudaGetSymbolAddress((void**)&h1,  g_h1);
    cudaGetSymbolAddress((void**)&h2,  g_h2);
    cudaGetSymbolAddress((void**)&w0,  g_w0);
    cudaGetSymbolAddress((void**)&w1,  g_w1);
    cudaGetSymbolAddress((void**)&w2,  g_w2);
    cudaGetSymbolAddress((void**)&deg, g_deg);
    cudaGetSymbolAddress((void**)&off, g_off);
    cudaGetSymbolAddress((void**)&cur, g_cur);
    cudaGetSymbolAddress((void**)&srcs, g_srcs);
    cudaGetSymbolAddress((void**)&bsum, g_sum);
    cudaGetSymbolAddress((void**)&bsq,  g_sq);

    const int TB = 256;
    const int nodeBlocks = (NN + TB - 1) / TB;
    const int edgeBlocks = (EE + TB - 1) / TB;
    const int warpNodeBlocks = (NN * 32 + TB - 1) / TB;

    // Fork: CSR build on s1 overlaps pack+gemm0 on main stream.
    cudaEventRecord(evFork, 0);
    cudaStreamWaitEvent(s1, evFork, 0);

    zero_int_bn_kernel<<<nodeBlocks, TB, 0, s1>>>(deg, NN, bsum, bsq);
    count_deg_kernel<<<edgeBlocks, TB, 0, s1>>>(dst, deg, EE);
    scan_kernel<<<1, 1024, 0, s1>>>(deg, off, cur, NN);
    scatter_kernel<<<edgeBlocks, TB, 0, s1>>>(src, dst, cur, srcs, EE);
    cudaEventRecord(evJoin, s1);

    pack_all_kernel<<<(PACK_TOTAL + TB - 1) / TB, TB>>>(
        Wsrc0, Wdst0, resW0, Wsrc1, Wdst1, Wsrc2, Wdst2, resW2, w0, w1, w2);
    launch_gemm<false>(x, w0, cmb, NN, 768, 128,
                       nullptr, nullptr, nullptr, nullptr, 0.f, 0);

    cudaStreamWaitEvent(0, evJoin, 0);

    // ---- layer 0 edges (+BN stats -> slot 0); h1 stays RAW ----
    gat_edge_kernel<8, true, true, true, false, false><<<warpNodeBlocks, TB>>>(
        cmb, cmb + 256, cmb + 512, 768, 768, b0, attn0,
        nullptr, nullptr, nullptr, nullptr, 0.f,
        off, srcs, h1, bsum, bsq, NN);

    // ---- layer 1: GEMM computes+applies BN0 inline; edge does RESBN inline,
    //      stats -> slot 1 ----
    launch_gemm<true>(h1, w1, cmb, NN, 512, 256,
                      bsum, bsq, g0, be0, inv_n, 0);
    gat_edge_kernel<8, true, true, true, false, true><<<warpNodeBlocks, TB>>>(
        cmb, cmb + 256, h1, 512, 256, b1, attn1,
        bsum, bsq, g0, be0, inv_n,
        off, srcs, h2, bsum + 256, bsq + 256, NN);

    // ---- layer 2: GEMM computes+applies BN1 inline; fused final edge ----
    launch_gemm<true>(h2, w2, cmb, NN, 480, 256,
                      bsum + 256, bsq + 256, g1, be1, inv_n, 0);
    gat_edge_kernel<5, false, false, false, true, false><<<warpNodeBlocks, TB>>>(
        cmb, cmb + 160, cmb + 320, 480, 480, b2, attn2,
        nullptr, nullptr, nullptr, nullptr, 0.f,
        off, srcs, out, nullptr, nullptr, NN);

    (void)n_in; (void)out_size;
}